// round 3
// baseline (speedup 1.0000x reference)
#include <cuda_runtime.h>
#include <cstdint>

#define BB 4
#define GG 8
#define NVOX 110592            /* 48*48*48 */
#define NELEM 331776           /* NVOX*3 */
#define NU4 (NELEM/4)          /* 82944 */
#define KTOP 800
#define NT 512
#define BPS 74                 /* blocks per sample */
#define NBLK (BPS*BB)          /* 296 */
#define NTILES 216             /* NVOX/512 */

// ---------------- device scratch (static, zero-init, self-cleaning) ----------
__device__ unsigned g_u[BB*NELEM];
__device__ unsigned g_list[BB*NELEM];
__device__ unsigned g_hist1[BB][2048];
__device__ float    g_pos_sum[BB];
__device__ float    g_reg_sum[BB];
__device__ float    g_topsum[BB];
__device__ float    g_neg[BB];
__device__ float    g_kcnt[BB];
__device__ unsigned g_npos[BB];
__device__ unsigned g_k2[BB];
__device__ unsigned g_listn[BB];
__device__ int      g_done[BB];
__device__ int      g_b1[BB];
__device__ unsigned g_arriveA[BB];
__device__ unsigned g_arriveB[BB];
__device__ unsigned g_arriveF;
__device__ unsigned g_flagA[BB];

// ---------------- helpers ----------------
__device__ __forceinline__ float softplus0(float x) {
    return fmaxf(x, 0.0f) + log1pf(expf(-fabsf(x)));
}
__device__ __forceinline__ float sl1(float x) {
    float ax = fabsf(x);
    return (ax < 1.0f) ? 0.5f * x * x : ax - 0.5f;
}
__device__ __forceinline__ unsigned ordmap(float f) {
    unsigned bb = __float_as_uint(f);
    return (bb & 0x80000000u) ? ~bb : (bb | 0x80000000u);
}
__device__ __forceinline__ float unord(unsigned u) {
    unsigned bb = (u & 0x80000000u) ? (u ^ 0x80000000u) : ~u;
    return __uint_as_float(bb);
}
__device__ __forceinline__ unsigned wscan_incl(unsigned v, int lane) {
#pragma unroll
    for (int o = 1; o < 32; o <<= 1) {
        unsigned t = __shfl_up_sync(0xffffffffu, v, o);
        if (lane >= o) v += t;
    }
    return v;
}

// ================= single fused persistent kernel =============
__global__ void __launch_bounds__(NT, 2)
k_fused(const float* __restrict__ pred, const float* __restrict__ tgt,
        float* __restrict__ out) {
    __shared__ float4 s_stage[1920];                       // 30720 B (reused as sh3 in tail)
    __shared__ unsigned s_hist[2048];                      // 8 KB (reused as sh2 in tail)
    __shared__ float s_gx[GG], s_gy[GG], s_gz[GG], s_gd[GG], s_d3[GG];
    __shared__ float s_gxp[GG], s_gxm[GG], s_gyp[GG], s_gym[GG], s_gzp[GG], s_gzm[GG];
    __shared__ int s_lastA, s_lastB, s_fin, s_b2;
    __shared__ unsigned s_k3;
    __shared__ float s_acc;

    const int tid  = threadIdx.x;
    const int lane = tid & 31;
    const int b    = blockIdx.x / BPS;
    const int j    = blockIdx.x % BPS;

    if (tid < GG) {
        const float* t = tgt + (b * GG + tid) * 4;
        float gx = t[0], gy = t[1], gz = t[2], gd = t[3];
        float r2 = 0.5f * gd;
        s_gx[tid] = gx; s_gy[tid] = gy; s_gz[tid] = gz; s_gd[tid] = gd;
        s_gxp[tid] = gx + r2; s_gxm[tid] = gx - r2;
        s_gyp[tid] = gy + r2; s_gym[tid] = gy - r2;
        s_gzp[tid] = gz + r2; s_gzm[tid] = gz - r2;
        s_d3[tid] = gd * gd * gd;
    }
    for (int i = tid; i < 2048; i += NT) s_hist[i] = 0u;

    const float r1s[3]  = {2.5f, 5.0f, 10.0f};
    const float a3s[3]  = {125.0f, 1000.0f, 8000.0f};
    const float inva[3] = {0.2f, 0.1f, 0.05f};

    float lpos = 0.0f, lreg = 0.0f;
    unsigned lnp = 0;

    // ---------------- phase 1: main pass ----------------
    for (int t = j; t < NTILES; t += BPS) {
        const int vbase = t * NT;
        const float4* src = (const float4*)(pred + ((size_t)b * NVOX + (size_t)vbase) * 15);
#pragma unroll
        for (int i2 = 0; i2 < 4; i2++) {
            int idx = tid + i2 * NT;
            if (idx < 1920) s_stage[idx] = src[idx];
        }
        __syncthreads();

        const float* sv = ((const float*)s_stage) + tid * 15;
        const int vox = vbase + tid;
        const int w = vox % 48; const int t2 = vox / 48;
        const int h = t2 % 48;  const int d = t2 / 48;
        const float cx = (float)(w * 4 + 2);
        const float cy = (float)(h * 4 + 2);
        const float cz = (float)(d * 4 + 2);

        float bi[3], bu[3]; int bidx[3];
#pragma unroll
        for (int a = 0; a < 3; a++) { bi[a] = -1.0f; bu[a] = 1.0f; bidx[a] = 0; }

#pragma unroll
        for (int g = 0; g < GG; g++) {
            float xp = s_gxp[g], xm = s_gxm[g];
            float yp = s_gyp[g], ym = s_gym[g];
            float zp = s_gzp[g], zm = s_gzm[g];
            float d3 = s_d3[g];
#pragma unroll
            for (int a = 0; a < 3; a++) {
                float r1 = r1s[a];
                float ix = fminf(cx + r1, xp) - fmaxf(cx - r1, xm); ix = fmaxf(ix, 0.0f);
                float iy = fminf(cy + r1, yp) - fmaxf(cy - r1, ym); iy = fmaxf(iy, 0.0f);
                float iz = fminf(cz + r1, zp) - fmaxf(cz - r1, zm); iz = fmaxf(iz, 0.0f);
                float inter = ix * iy * iz;
                float un = a3s[a] + d3 - inter + 1e-6f;
                if (inter * bu[a] > bi[a] * un) { bi[a] = inter; bu[a] = un; bidx[a] = g; }
            }
        }

#pragma unroll
        for (int a = 0; a < 3; a++) {
            float conf = sv[a * 5];
            bool pos = bi[a] > 0.5f  * bu[a];
            bool neg = bi[a] < 0.02f * bu[a];
            unsigned u = 0u;
            if (neg) u = ordmap(conf);
            // warp-aggregated shared-hist update
            unsigned key = neg ? (u >> 21) : (0x40000000u | (unsigned)lane);
            unsigned peers = __match_any_sync(0xffffffffu, key);
            if (neg && (__ffs(peers) - 1 == lane))
                atomicAdd(&s_hist[key], (unsigned)__popc(peers));
            g_u[((size_t)(b * 3 + a)) * NVOX + vox] = u;
            if (pos) {
                lnp++;
                lpos += fmaxf(conf, 0.0f) - conf + log1pf(expf(-fabsf(conf)));
                int g = bidx[a];
                float ia = inva[a];
                float tx = (s_gx[g] - cx) * ia;
                float ty = (s_gy[g] - cy) * ia;
                float tz = (s_gz[g] - cz) * ia;
                float td = logf(s_gd[g] * ia);
                lreg += sl1(sv[a*5+1] - tx) + sl1(sv[a*5+2] - ty)
                      + sl1(sv[a*5+3] - tz) + sl1(sv[a*5+4] - td);
            }
        }
        __syncthreads();
    }

    // flush block hist to global
    for (int i = tid; i < 2048; i += NT) {
        unsigned c = s_hist[i];
        if (c) atomicAdd(&g_hist1[b][i], c);
    }
    // reduce pos accumulators (warp level)
#pragma unroll
    for (int o = 16; o; o >>= 1) {
        lpos += __shfl_down_sync(0xffffffffu, lpos, o);
        lreg += __shfl_down_sync(0xffffffffu, lreg, o);
        lnp  += __shfl_down_sync(0xffffffffu, lnp, o);
    }
    if (lane == 0 && lnp) {
        atomicAdd(&g_pos_sum[b], lpos);
        atomicAdd(&g_reg_sum[b], lreg);
        atomicAdd(&g_npos[b], lnp);
    }
    __threadfence();
    __syncthreads();
    if (tid == 0) s_lastA = (atomicAdd(&g_arriveA[b], 1u) == BPS - 1);
    __syncthreads();

    if (s_lastA) {
        __threadfence();   // acquire: see all blocks' hist
        if (tid < 32) {    // level-1 selection
            const int base1 = 2047 - 64 * lane;
            unsigned cc = 0;
#pragma unroll 8
            for (int q = 0; q < 64; q++) cc += __ldcg(&g_hist1[b][base1 - q]);
            unsigned pre = wscan_incl(cc, lane);
            unsigned excl = pre - cc;
            unsigned total = __shfl_sync(0xffffffffu, pre, 31);
            if (total <= KTOP) {
                if (lane == 0) { g_done[b] = 1; g_kcnt[b] = (float)total; }
            } else {
                if (lane == 0) { g_done[b] = 0; g_kcnt[b] = (float)KTOP; }
                bool cross = (excl < KTOP) && (pre >= KTOP);
                unsigned m = __ballot_sync(0xffffffffu, cross);
                int src = __ffs(m) - 1;
                if (lane == src) {
                    unsigned c = excl;
                    for (int q = 0; q < 64; q++) {
                        unsigned cnt = __ldcg(&g_hist1[b][base1 - q]);
                        if (c + cnt >= KTOP) { g_b1[b] = base1 - q; g_k2[b] = KTOP - c; break; }
                        c += cnt;
                    }
                }
            }
        }
        __syncthreads();
        for (int i = tid; i < 2048; i += NT) g_hist1[b][i] = 0u;   // self-clean
        if (tid == 0) g_arriveA[b] = 0u;
        __threadfence();
        __syncthreads();
        if (tid == 0) atomicExch(&g_flagA[b], 1u);
    } else {
        if (tid == 0) { while (atomicAdd(&g_flagA[b], 0u) == 0u) __nanosleep(64); }
        __syncthreads();
        __threadfence();   // acquire
    }

    // ---------------- phase 2: refine pass ----------------
    const int done = __ldcg(&g_done[b]);
    const int b1   = __ldcg(&g_b1[b]);

    const uint4* usrc = ((const uint4*)g_u) + (size_t)b * NU4;
    uint4 vv[3]; int ivalid[3];
#pragma unroll
    for (int k = 0; k < 3; k++) {
        int i = j * NT + tid + k * (BPS * NT);
        ivalid[k] = (i < NU4);
        if (ivalid[k]) vv[k] = usrc[i];
    }
    float s = 0.0f;
#pragma unroll
    for (int k = 0; k < 3; k++) {
        unsigned e[4] = {0u, 0u, 0u, 0u};
        if (ivalid[k]) { e[0] = vv[k].x; e[1] = vv[k].y; e[2] = vv[k].z; e[3] = vv[k].w; }
#pragma unroll
        for (int q = 0; q < 4; q++) {
            unsigned u = e[q];
            bool addsp = false, put = false;
            if (u) {
                if (done) addsp = true;
                else {
                    int tb = (int)(u >> 21);
                    if (tb > b1) addsp = true;
                    else if (tb == b1) put = true;
                }
            }
            if (addsp) s += softplus0(unord(u));
            unsigned m = __ballot_sync(0xffffffffu, put);
            if (m) {
                int leader = __ffs(m) - 1;
                unsigned base = 0u;
                if (lane == leader) base = atomicAdd(&g_listn[b], (unsigned)__popc(m));
                base = __shfl_sync(0xffffffffu, base, leader);
                if (put) g_list[(size_t)b * NELEM + base + __popc(m & ((1u << lane) - 1u))] = u;
            }
        }
    }
#pragma unroll
    for (int o = 16; o; o >>= 1) s += __shfl_down_sync(0xffffffffu, s, o);
    if (lane == 0 && s != 0.0f) atomicAdd(&g_topsum[b], s);

    __threadfence();
    __syncthreads();
    if (tid == 0) s_lastB = (atomicAdd(&g_arriveB[b], 1u) == BPS - 1);
    __syncthreads();
    if (!s_lastB) return;

    // ---------------- per-sample tail: exact in-bin top-k2 ----------------
    __threadfence();   // acquire
    const float kcnt = __ldcg(&g_kcnt[b]);
    unsigned* sh2 = s_hist;
    unsigned* sh3 = (unsigned*)s_stage;

    if (done) {
        if (tid == 0) g_neg[b] = (kcnt > 0.0f) ? __ldcg(&g_topsum[b]) / kcnt : 0.0f;
        __syncthreads();
    } else {
        const unsigned k2 = __ldcg(&g_k2[b]);
        const unsigned n  = __ldcg(&g_listn[b]);
        const unsigned* lst = g_list + (size_t)b * NELEM;

        for (int q = tid; q < 2048; q += NT) sh2[q] = 0u;
        __syncthreads();
        for (unsigned q = tid; q < n; q += NT)
            atomicAdd(&sh2[(__ldcg(&lst[q]) >> 10) & 0x7FFu], 1u);
        __syncthreads();

        if (tid < 32) {
            const int base2 = 2047 - 64 * lane;
            unsigned cc = 0;
#pragma unroll 8
            for (int q = 0; q < 64; q++) cc += sh2[base2 - q];
            unsigned pre = wscan_incl(cc, lane);
            unsigned excl = pre - cc;
            bool cross = (excl < k2) && (pre >= k2);
            unsigned m = __ballot_sync(0xffffffffu, cross);
            int src = __ffs(m) - 1;
            if (lane == src) {
                unsigned c = excl;
                for (int q = 0; q < 64; q++) {
                    unsigned cnt = sh2[base2 - q];
                    if (c + cnt >= k2) { s_b2 = base2 - q; s_k3 = k2 - c; break; }
                    c += cnt;
                }
            }
        }
        __syncthreads();
        const int b2 = s_b2;

        for (int q = tid; q < 1024; q += NT) sh3[q] = 0u;
        if (tid == 0) s_acc = 0.0f;
        __syncthreads();

        float s2 = 0.0f;
        for (unsigned q = tid; q < n; q += NT) {
            unsigned u = __ldcg(&lst[q]);
            int m = (int)((u >> 10) & 0x7FFu);
            if (m > b2) s2 += softplus0(unord(u));
            else if (m == b2) atomicAdd(&sh3[u & 0x3FFu], 1u);
        }
#pragma unroll
        for (int o = 16; o; o >>= 1) s2 += __shfl_down_sync(0xffffffffu, s2, o);
        if (lane == 0 && s2 != 0.0f) atomicAdd(&s_acc, s2);
        __syncthreads();

        if (tid < 32) {
            const unsigned k = s_k3;
            const unsigned pref = ((unsigned)b1 << 21) | ((unsigned)b2 << 10);
            const int base3 = 1023 - 32 * lane;
            unsigned cc = 0;
            float ws = 0.0f;
            for (int q = 0; q < 32; q++) {
                unsigned cnt = sh3[base3 - q];
                if (cnt) ws += (float)cnt * softplus0(unord(pref | (unsigned)(base3 - q)));
                cc += cnt;
            }
            unsigned pre = wscan_incl(cc, lane);
            unsigned excl = pre - cc;
            float contrib;
            if (pre <= k) contrib = ws;
            else if (excl >= k) contrib = 0.0f;
            else {
                unsigned c = excl;
                contrib = 0.0f;
                for (int q = 0; q < 32; q++) {
                    unsigned cnt = sh3[base3 - q];
                    if (!cnt) continue;
                    float sp = softplus0(unord(pref | (unsigned)(base3 - q)));
                    if (c + cnt >= k) { contrib += (float)(k - c) * sp; break; }
                    contrib += (float)cnt * sp;
                    c += cnt;
                }
            }
#pragma unroll
            for (int o = 16; o; o >>= 1)
                contrib += __shfl_down_sync(0xffffffffu, contrib, o);
            if (lane == 0) g_neg[b] = (__ldcg(&g_topsum[b]) + s_acc + contrib) / kcnt;
        }
        __syncthreads();
    }

    // per-sample cleanup, then cross-sample finalize
    if (tid == 0) { g_listn[b] = 0u; g_arriveB[b] = 0u; g_flagA[b] = 0u; }
    __threadfence();
    __syncthreads();
    if (tid == 0) s_fin = (atomicAdd(&g_arriveF, 1u) == BB - 1);
    __syncthreads();
    if (s_fin && tid == 0) {
        __threadfence();   // acquire
        float cls = 0.0f, reg = 0.0f, npsum = 0.0f;
        for (int bb = 0; bb < BB; bb++) {
            float np = (float)__ldcg(&g_npos[bb]);
            float pl = (np > 0.0f) ? 5.0f * __ldcg(&g_pos_sum[bb]) / np : 0.0f;
            float rl = (np > 0.0f) ? __ldcg(&g_reg_sum[bb]) / (4.0f * np) : 0.0f;
            cls += pl + __ldcg(&g_neg[bb]);
            reg += rl;
            npsum += np;
            g_pos_sum[bb] = 0.0f; g_reg_sum[bb] = 0.0f;
            g_topsum[bb] = 0.0f;  g_npos[bb] = 0u;
        }
        g_arriveF = 0u;
        cls *= 0.25f;
        reg *= 0.25f;
        out[0] = cls + 0.5f * reg;
        out[1] = cls;
        out[2] = reg;
        out[3] = npsum;
    }
}

// ---------------- launcher ----------------
extern "C" void kernel_launch(void* const* d_in, const int* in_sizes, int n_in,
                              void* d_out, int out_size) {
    const float* pred = (const float*)d_in[0];   // (4,48,48,48,3,5)
    const float* tgt  = (const float*)d_in[1];   // (4,8,4)
    float* out = (float*)d_out;
    k_fused<<<NBLK, NT>>>(pred, tgt, out);
}

// round 5
// speedup vs baseline: 1.0628x; 1.0628x over previous
#include <cuda_runtime.h>
#include <cstdint>

#define BB 4
#define GG 8
#define NVOX 110592            /* 48*48*48 */
#define NELEM 331776           /* NVOX*3 */
#define NU4 (NELEM/4)          /* 82944 */
#define KTOP 800
#define VPB 768                /* voxels per block (3 chunks of 256) */
#define APB (NVOX/VPB)         /* 144 blocks per sample */
#define BITER 8
#define BPSB ((NU4 + 256*BITER - 1)/(256*BITER))   /* 41 */

// ---------------- device scratch (static, zero-init, self-cleaning) ----------
__device__ unsigned g_u[BB*NELEM];
__device__ unsigned g_list[BB*NELEM];
__device__ unsigned g_hist1[BB][2048];
__device__ float    g_pos_sum[BB];
__device__ float    g_reg_sum[BB];
__device__ float    g_topsum[BB];
__device__ float    g_neg[BB];
__device__ float    g_kcnt[BB];
__device__ unsigned g_npos[BB];
__device__ unsigned g_k2[BB];
__device__ unsigned g_listn[BB];
__device__ int      g_done[BB];
__device__ int      g_b1[BB];
__device__ unsigned g_arriveA[BB];
__device__ unsigned g_arriveB[BB];
__device__ unsigned g_arriveF;

// ---------------- helpers ----------------
__device__ __forceinline__ float softplus0(float x) {
    return fmaxf(x, 0.0f) + log1pf(expf(-fabsf(x)));
}
__device__ __forceinline__ float sl1(float x) {
    float ax = fabsf(x);
    return (ax < 1.0f) ? 0.5f * x * x : ax - 0.5f;
}
__device__ __forceinline__ unsigned ordmap(float f) {
    unsigned bb = __float_as_uint(f);
    return (bb & 0x80000000u) ? ~bb : (bb | 0x80000000u);
}
__device__ __forceinline__ float unord(unsigned u) {
    unsigned bb = (u & 0x80000000u) ? (u ^ 0x80000000u) : ~u;
    return __uint_as_float(bb);
}
__device__ __forceinline__ unsigned wscan_incl(unsigned v, int lane) {
#pragma unroll
    for (int o = 1; o < 32; o <<= 1) {
        unsigned t = __shfl_up_sync(0xffffffffu, v, o);
        if (lane >= o) v += t;
    }
    return v;
}

// ================= kernel A: main pass + fused level-1 selection =============
// grid (APB, BB), 256 threads; each block: 768 voxels in 3 staged chunks
__global__ void __launch_bounds__(256) k_A(const float* __restrict__ pred,
                                           const float* __restrict__ tgt) {
    __shared__ float s_stage[3840];          // 15360 B: 256 voxels x 15 floats
    __shared__ unsigned s_hist[2048];        // 8192 B
    __shared__ float sIx[1152], sIy[1152], sIz[1152];   // 24 combos x 48 coords
    __shared__ float s_s[24];                // a3 + d3 + 1e-6 per combo
    __shared__ float s_gx[GG], s_gy[GG], s_gz[GG], s_gd[GG];
    __shared__ int s_last;

    const int b   = blockIdx.y;
    const int j   = blockIdx.x;
    const int tid = threadIdx.x;
    const int lane = tid & 31;

    if (tid < GG) {
        const float* t = tgt + (b * GG + tid) * 4;
        s_gx[tid] = t[0]; s_gy[tid] = t[1]; s_gz[tid] = t[2]; s_gd[tid] = t[3];
    }
    for (int i = tid; i < 2048; i += 256) s_hist[i] = 0u;
    __syncthreads();

    // build per-dimension intersection tables: combo = a*8+g, coord 0..47
    for (int idx = tid; idx < 1152; idx += 256) {
        int combo = idx / 48;
        int coord = idx - combo * 48;
        int a = combo >> 3, g = combo & 7;
        float r1 = 2.5f * (float)(1 << a);
        float c  = (float)(coord * 4 + 2);
        float r2 = 0.5f * s_gd[g];
        float gx = s_gx[g], gy = s_gy[g], gz = s_gz[g];
        sIx[idx] = fmaxf(fminf(c + r1, gx + r2) - fmaxf(c - r1, gx - r2), 0.0f);
        sIy[idx] = fmaxf(fminf(c + r1, gy + r2) - fmaxf(c - r1, gy - r2), 0.0f);
        sIz[idx] = fmaxf(fminf(c + r1, gz + r2) - fmaxf(c - r1, gz - r2), 0.0f);
    }
    if (tid < 24) {
        int a = tid >> 3, g = tid & 7;
        float d5 = 5.0f * (float)(1 << a);           // anchor diameter
        float gd = s_gd[g];
        s_s[tid] = d5 * d5 * d5 + gd * gd * gd + 1e-6f;
    }
    __syncthreads();

    const float inva[3] = {0.2f, 0.1f, 0.05f};
    float lpos = 0.0f, lreg = 0.0f;
    unsigned lnp = 0;

#pragma unroll
    for (int cch = 0; cch < 3; cch++) {
        const int vbase = j * VPB + cch * 256;
        const float4* src = (const float4*)(pred + ((size_t)b * NVOX + (size_t)vbase) * 15);
#pragma unroll
        for (int i = 0; i < 4; i++) {
            int idx = tid + i * 256;
            if (idx < 960) ((float4*)s_stage)[idx] = src[idx];
        }
        __syncthreads();

        const int vox = vbase + tid;
        const int w = vox % 48; const int t2 = vox / 48;
        const int h = t2 % 48;  const int d = t2 / 48;
        const float* sv = s_stage + tid * 15;

        float bi[3], bu[3]; int bidx[3];
#pragma unroll
        for (int a = 0; a < 3; a++) { bi[a] = -1.0f; bu[a] = 1.0f; bidx[a] = 0; }

#pragma unroll
        for (int g = 0; g < GG; g++) {
#pragma unroll
            for (int a = 0; a < 3; a++) {
                const int combo = a * 8 + g;
                float inter = sIx[combo*48 + w] * sIy[combo*48 + h] * sIz[combo*48 + d];
                float un = s_s[combo] - inter;
                if (inter * bu[a] > bi[a] * un) { bi[a] = inter; bu[a] = un; bidx[a] = g; }
            }
        }

        const float cx = (float)(w * 4 + 2);
        const float cy = (float)(h * 4 + 2);
        const float cz = (float)(d * 4 + 2);
#pragma unroll
        for (int a = 0; a < 3; a++) {
            float conf = sv[a * 5];
            bool pos = bi[a] > 0.5f  * bu[a];
            bool neg = bi[a] < 0.02f * bu[a];
            unsigned u = 0u;
            if (neg) { u = ordmap(conf); atomicAdd(&s_hist[u >> 21], 1u); }
            g_u[((size_t)(b * 3 + a)) * NVOX + vox] = u;
            if (pos) {
                lnp++;
                lpos += fmaxf(conf, 0.0f) - conf + log1pf(expf(-fabsf(conf)));
                int g = bidx[a];
                float ia = inva[a];
                float tx = (s_gx[g] - cx) * ia;
                float ty = (s_gy[g] - cy) * ia;
                float tz = (s_gz[g] - cz) * ia;
                float td = logf(s_gd[g] * ia);
                lreg += sl1(sv[a*5+1] - tx) + sl1(sv[a*5+2] - ty)
                      + sl1(sv[a*5+3] - tz) + sl1(sv[a*5+4] - td);
            }
        }
        __syncthreads();
    }

    // flush block hist to global
    for (int i = tid; i < 2048; i += 256) {
        unsigned c = s_hist[i];
        if (c) atomicAdd(&g_hist1[b][i], c);
    }
#pragma unroll
    for (int o = 16; o; o >>= 1) {
        lpos += __shfl_down_sync(0xffffffffu, lpos, o);
        lreg += __shfl_down_sync(0xffffffffu, lreg, o);
        lnp  += __shfl_down_sync(0xffffffffu, lnp, o);
    }
    if (lane == 0 && lnp) {
        atomicAdd(&g_pos_sum[b], lpos);
        atomicAdd(&g_reg_sum[b], lreg);
        atomicAdd(&g_npos[b], lnp);
    }
    __threadfence();
    __syncthreads();
    if (tid == 0) s_last = (atomicAdd(&g_arriveA[b], 1u) == APB - 1);
    __syncthreads();
    if (!s_last) return;

    __threadfence();   // acquire: see all blocks' hist
    if (tid < 32) {    // level-1 selection
        const int base1 = 2047 - 64 * lane;
        unsigned cc = 0;
#pragma unroll 8
        for (int q = 0; q < 64; q++) cc += __ldcg(&g_hist1[b][base1 - q]);
        unsigned pre = wscan_incl(cc, lane);
        unsigned excl = pre - cc;
        unsigned total = __shfl_sync(0xffffffffu, pre, 31);
        if (total <= KTOP) {
            if (lane == 0) { g_done[b] = 1; g_kcnt[b] = (float)total; }
        } else {
            if (lane == 0) { g_done[b] = 0; g_kcnt[b] = (float)KTOP; }
            bool cross = (excl < KTOP) && (pre >= KTOP);
            unsigned m = __ballot_sync(0xffffffffu, cross);
            int src = __ffs(m) - 1;
            if (lane == src) {
                unsigned c = excl;
                for (int q = 0; q < 64; q++) {
                    unsigned cnt = __ldcg(&g_hist1[b][base1 - q]);
                    if (c + cnt >= KTOP) { g_b1[b] = base1 - q; g_k2[b] = KTOP - c; break; }
                    c += cnt;
                }
            }
        }
    }
    __syncthreads();
    for (int i = tid; i < 2048; i += 256) g_hist1[b][i] = 0u;   // self-clean
    if (tid == 0) g_arriveA[b] = 0u;
}

// ================= kernel B: refine pass + fused exact in-bin select + final ==
// grid (BPSB, BB), 256 threads; each thread loads 8 independent uint4 (MLP 8)
__global__ void __launch_bounds__(256) k_B(float* __restrict__ out) {
    __shared__ unsigned sh2[2048];
    __shared__ unsigned sh3[1024];
    __shared__ float s_acc;
    __shared__ int s_last, s_fin, s_b2;
    __shared__ unsigned s_k3;

    const int b   = blockIdx.y;
    const int tid = threadIdx.x;
    const int lane = tid & 31;
    const int done = g_done[b];
    const int b1   = g_b1[b];

    const uint4* usrc = ((const uint4*)g_u) + (size_t)b * NU4;
    const int base = blockIdx.x * (256 * BITER) + tid;
    uint4 vv[BITER];
#pragma unroll
    for (int k = 0; k < BITER; k++) {
        int i = base + k * 256;
        vv[k] = (i < NU4) ? usrc[i] : make_uint4(0u, 0u, 0u, 0u);
    }
    float s = 0.0f;
#pragma unroll
    for (int k = 0; k < BITER; k++) {
        unsigned e[4] = {vv[k].x, vv[k].y, vv[k].z, vv[k].w};
#pragma unroll
        for (int q = 0; q < 4; q++) {
            unsigned u = e[q];
            if (!u) continue;
            if (done) {
                s += softplus0(unord(u));
            } else {
                int tb = (int)(u >> 21);
                if (tb > b1) s += softplus0(unord(u));
                else if (tb == b1) {
                    unsigned idx = atomicAdd(&g_listn[b], 1u);
                    g_list[(size_t)b * NELEM + idx] = u;
                }
            }
        }
    }
#pragma unroll
    for (int o = 16; o; o >>= 1) s += __shfl_down_sync(0xffffffffu, s, o);
    if (lane == 0 && s != 0.0f) atomicAdd(&g_topsum[b], s);

    __threadfence();
    __syncthreads();
    if (tid == 0) s_last = (atomicAdd(&g_arriveB[b], 1u) == BPSB - 1);
    __syncthreads();
    if (!s_last) return;

    // ---- per-sample tail: exact in-bin top-k2 ----
    __threadfence();   // acquire
    const float kcnt = __ldcg(&g_kcnt[b]);

    if (done) {
        if (tid == 0) g_neg[b] = (kcnt > 0.0f) ? __ldcg(&g_topsum[b]) / kcnt : 0.0f;
        __syncthreads();
    } else {
        const unsigned k2 = __ldcg(&g_k2[b]);
        const unsigned n  = __ldcg(&g_listn[b]);
        const unsigned* lst = g_list + (size_t)b * NELEM;

        for (int q = tid; q < 2048; q += 256) sh2[q] = 0u;
        __syncthreads();
        for (unsigned q = tid; q < n; q += 256)
            atomicAdd(&sh2[(__ldcg(&lst[q]) >> 10) & 0x7FFu], 1u);
        __syncthreads();

        if (tid < 32) {
            const int base2 = 2047 - 64 * lane;
            unsigned cc = 0;
#pragma unroll 8
            for (int q = 0; q < 64; q++) cc += sh2[base2 - q];
            unsigned pre = wscan_incl(cc, lane);
            unsigned excl = pre - cc;
            bool cross = (excl < k2) && (pre >= k2);
            unsigned m = __ballot_sync(0xffffffffu, cross);
            int src = __ffs(m) - 1;
            if (lane == src) {
                unsigned c = excl;
                for (int q = 0; q < 64; q++) {
                    unsigned cnt = sh2[base2 - q];
                    if (c + cnt >= k2) { s_b2 = base2 - q; s_k3 = k2 - c; break; }
                    c += cnt;
                }
            }
        }
        __syncthreads();
        const int b2 = s_b2;

        for (int q = tid; q < 1024; q += 256) sh3[q] = 0u;
        if (tid == 0) s_acc = 0.0f;
        __syncthreads();

        float s2 = 0.0f;
        for (unsigned q = tid; q < n; q += 256) {
            unsigned u = __ldcg(&lst[q]);
            int m = (int)((u >> 10) & 0x7FFu);
            if (m > b2) s2 += softplus0(unord(u));
            else if (m == b2) atomicAdd(&sh3[u & 0x3FFu], 1u);
        }
#pragma unroll
        for (int o = 16; o; o >>= 1) s2 += __shfl_down_sync(0xffffffffu, s2, o);
        if (lane == 0 && s2 != 0.0f) atomicAdd(&s_acc, s2);
        __syncthreads();

        if (tid < 32) {
            const unsigned k = s_k3;
            const unsigned pref = ((unsigned)b1 << 21) | ((unsigned)b2 << 10);
            const int base3 = 1023 - 32 * lane;
            unsigned cc = 0;
            float ws = 0.0f;
            for (int q = 0; q < 32; q++) {
                unsigned cnt = sh3[base3 - q];
                if (cnt) ws += (float)cnt * softplus0(unord(pref | (unsigned)(base3 - q)));
                cc += cnt;
            }
            unsigned pre = wscan_incl(cc, lane);
            unsigned excl = pre - cc;
            float contrib;
            if (pre <= k) contrib = ws;
            else if (excl >= k) contrib = 0.0f;
            else {
                unsigned c = excl;
                contrib = 0.0f;
                for (int q = 0; q < 32; q++) {
                    unsigned cnt = sh3[base3 - q];
                    if (!cnt) continue;
                    float sp = softplus0(unord(pref | (unsigned)(base3 - q)));
                    if (c + cnt >= k) { contrib += (float)(k - c) * sp; break; }
                    contrib += (float)cnt * sp;
                    c += cnt;
                }
            }
#pragma unroll
            for (int o = 16; o; o >>= 1)
                contrib += __shfl_down_sync(0xffffffffu, contrib, o);
            if (lane == 0) g_neg[b] = (__ldcg(&g_topsum[b]) + s_acc + contrib) / kcnt;
        }
        __syncthreads();
    }

    // per-sample cleanup, then cross-sample finalize
    if (tid == 0) { g_listn[b] = 0u; g_arriveB[b] = 0u; }
    __threadfence();
    __syncthreads();
    if (tid == 0) s_fin = (atomicAdd(&g_arriveF, 1u) == BB - 1);
    __syncthreads();
    if (s_fin && tid == 0) {
        __threadfence();   // acquire
        float cls = 0.0f, reg = 0.0f, npsum = 0.0f;
        for (int bb = 0; bb < BB; bb++) {
            float np = (float)__ldcg(&g_npos[bb]);
            float pl = (np > 0.0f) ? 5.0f * __ldcg(&g_pos_sum[bb]) / np : 0.0f;
            float rl = (np > 0.0f) ? __ldcg(&g_reg_sum[bb]) / (4.0f * np) : 0.0f;
            cls += pl + __ldcg(&g_neg[bb]);
            reg += rl;
            npsum += np;
            g_pos_sum[bb] = 0.0f; g_reg_sum[bb] = 0.0f;
            g_topsum[bb] = 0.0f;  g_npos[bb] = 0u;
        }
        g_arriveF = 0u;
        cls *= 0.25f;
        reg *= 0.25f;
        out[0] = cls + 0.5f * reg;
        out[1] = cls;
        out[2] = reg;
        out[3] = npsum;
    }
}

// ---------------- launcher ----------------
extern "C" void kernel_launch(void* const* d_in, const int* in_sizes, int n_in,
                              void* d_out, int out_size) {
    const float* pred = (const float*)d_in[0];   // (4,48,48,48,3,5)
    const float* tgt  = (const float*)d_in[1];   // (4,8,4)
    float* out = (float*)d_out;

    dim3 ga(APB, BB);          // 144 x 4
    k_A<<<ga, 256>>>(pred, tgt);
    dim3 gb(BPSB, BB);         // 41 x 4
    k_B<<<gb, 256>>>(out);
}

// round 6
// speedup vs baseline: 1.1997x; 1.1289x over previous
#include <cuda_runtime.h>
#include <cstdint>

#define BB 4
#define GG 8
#define NVOX 110592            /* 48*48*48 */
#define NELEM 331776           /* NVOX*3 */
#define NU4 (NELEM/4)          /* 82944 */
#define KTOP 800
#define APB (NELEM/256)        /* 1296 blocks per sample, kernel A */
#define BPB (NU4/256)          /* 324 blocks per sample, kernel B */

// ---------------- device scratch (static, zero-init, self-cleaning) ----------
__device__ unsigned g_u[BB*NELEM];
__device__ unsigned g_list[BB*NELEM];
__device__ unsigned g_hist1[BB][2048];
__device__ unsigned g_hist2[BB][2048];
__device__ float    g_pos_sum[BB];
__device__ float    g_reg_sum[BB];
__device__ float    g_topsum[BB];
__device__ float    g_neg[BB];
__device__ float    g_kcnt[BB];
__device__ unsigned g_npos[BB];
__device__ unsigned g_k2[BB];
__device__ unsigned g_listn[BB];
__device__ int      g_done[BB];
__device__ int      g_b1[BB];
__device__ unsigned g_arriveA[BB];
__device__ unsigned g_arriveB[BB];
__device__ unsigned g_arriveF;

// ---------------- helpers ----------------
__device__ __forceinline__ float softplus0(float x) {
    return fmaxf(x, 0.0f) + log1pf(expf(-fabsf(x)));
}
__device__ __forceinline__ float sl1(float x) {
    float ax = fabsf(x);
    return (ax < 1.0f) ? 0.5f * x * x : ax - 0.5f;
}
__device__ __forceinline__ unsigned ordmap(float f) {
    unsigned bb = __float_as_uint(f);
    return (bb & 0x80000000u) ? ~bb : (bb | 0x80000000u);
}
__device__ __forceinline__ float unord(unsigned u) {
    unsigned bb = (u & 0x80000000u) ? (u ^ 0x80000000u) : ~u;
    return __uint_as_float(bb);
}
__device__ __forceinline__ unsigned wscan_incl(unsigned v, int lane) {
#pragma unroll
    for (int o = 1; o < 32; o <<= 1) {
        unsigned t = __shfl_up_sync(0xffffffffu, v, o);
        if (lane >= o) v += t;
    }
    return v;
}
// block-wide inclusive scan over 256 threads (thread 0 = topmost chunk).
// s_w must have >= 16 entries; contains garbage afterwards.
__device__ __forceinline__ unsigned bscan(unsigned v, unsigned* s_w, int tid, int lane) {
    unsigned pre = wscan_incl(v, lane);
    if (lane == 31) s_w[tid >> 5] = pre;
    __syncthreads();
    if (tid < 32) {
        unsigned t = (tid < 8) ? s_w[tid] : 0u;
        unsigned p = wscan_incl(t, tid);
        if (tid < 8) s_w[tid + 8] = p - t;      // exclusive warp offset
    }
    __syncthreads();
    return pre + s_w[8 + (tid >> 5)];
}

// ================= kernel A: per-element main pass + parallel level-1 select =
// grid (APB, BB), 256 threads, one (voxel, anchor) element per thread
__global__ void __launch_bounds__(256) k_A(const float* __restrict__ pred,
                                           const float* __restrict__ tgt) {
    __shared__ float s_gxp[GG], s_gxm[GG], s_gyp[GG], s_gym[GG], s_gzp[GG], s_gzm[GG];
    __shared__ float s_gx[GG], s_gy[GG], s_gz[GG], s_gd[GG], s_d3[GG];
    __shared__ unsigned s_hist[2048];
    __shared__ unsigned s_w[16];
    __shared__ unsigned s_total;
    __shared__ int s_last;

    const int b    = blockIdx.y;
    const int tid  = threadIdx.x;
    const int lane = tid & 31;

    if (tid < GG) {
        const float* t = tgt + (b * GG + tid) * 4;
        float gx = t[0], gy = t[1], gz = t[2], gd = t[3];
        float r2 = 0.5f * gd;
        s_gx[tid] = gx; s_gy[tid] = gy; s_gz[tid] = gz; s_gd[tid] = gd;
        s_gxp[tid] = gx + r2; s_gxm[tid] = gx - r2;
        s_gyp[tid] = gy + r2; s_gym[tid] = gy - r2;
        s_gzp[tid] = gz + r2; s_gzm[tid] = gz - r2;
        s_d3[tid] = gd * gd * gd;
    }
    for (int i = tid; i < 2048; i += 256) s_hist[i] = 0u;
    __syncthreads();

    const int e   = blockIdx.x * 256 + tid;          // element = vox*3 + a
    const int vox = e / 3;
    const int a   = e - vox * 3;
    const int w = vox % 48; const int t2 = vox / 48;
    const int h = t2 % 48;  const int d = t2 / 48;
    const float cx = (float)(w * 4 + 2);
    const float cy = (float)(h * 4 + 2);
    const float cz = (float)(d * 4 + 2);

    const float r1 = 2.5f * (float)(1 << a);                         // anchor/2
    const float a3 = 125.0f * (float)(1 << (3 * a));                 // anchor^3
    const float ia = __uint_as_float(0x3E4CCCCDu - ((unsigned)a << 23)); // 0.2/2^a

    const float* p = pred + ((size_t)b * NELEM + (size_t)e) * 5;
    const float conf = p[0];

    float bi = -1.0f, bu = 1.0f;
    int bidx = 0;
#pragma unroll
    for (int g = 0; g < GG; g++) {
        float ix = fminf(cx + r1, s_gxp[g]) - fmaxf(cx - r1, s_gxm[g]); ix = fmaxf(ix, 0.0f);
        float iy = fminf(cy + r1, s_gyp[g]) - fmaxf(cy - r1, s_gym[g]); iy = fmaxf(iy, 0.0f);
        float iz = fminf(cz + r1, s_gzp[g]) - fmaxf(cz - r1, s_gzm[g]); iz = fmaxf(iz, 0.0f);
        float inter = ix * iy * iz;
        float un = a3 + s_d3[g] - inter + 1e-6f;
        if (inter * bu > bi * un) { bi = inter; bu = un; bidx = g; }
    }

    const bool pos = bi > 0.5f  * bu;
    const bool neg = bi < 0.02f * bu;
    unsigned u = 0u;
    if (neg) { u = ordmap(conf); atomicAdd(&s_hist[u >> 21], 1u); }
    g_u[(size_t)b * NELEM + e] = u;

    float lpos = 0.0f, lreg = 0.0f;
    unsigned lnp = 0;
    if (pos) {
        lnp = 1;
        lpos = fmaxf(conf, 0.0f) - conf + log1pf(expf(-fabsf(conf)));
        int g = bidx;
        float tx = (s_gx[g] - cx) * ia;
        float ty = (s_gy[g] - cy) * ia;
        float tz = (s_gz[g] - cz) * ia;
        float td = logf(s_gd[g] * ia);
        lreg = sl1(p[1] - tx) + sl1(p[2] - ty) + sl1(p[3] - tz) + sl1(p[4] - td);
    }
#pragma unroll
    for (int o = 16; o; o >>= 1) {
        lpos += __shfl_down_sync(0xffffffffu, lpos, o);
        lreg += __shfl_down_sync(0xffffffffu, lreg, o);
        lnp  += __shfl_down_sync(0xffffffffu, lnp, o);
    }
    if (lane == 0 && lnp) {
        atomicAdd(&g_pos_sum[b], lpos);
        atomicAdd(&g_reg_sum[b], lreg);
        atomicAdd(&g_npos[b], lnp);
    }
    __syncthreads();
    for (int i = tid; i < 2048; i += 256) {
        unsigned c = s_hist[i];
        if (c) atomicAdd(&g_hist1[b][i], c);
    }
    __threadfence();
    __syncthreads();
    if (tid == 0) s_last = (atomicAdd(&g_arriveA[b], 1u) == APB - 1);
    __syncthreads();
    if (!s_last) return;

    // ---- parallel level-1 selection: 8 bins per thread, descending ----
    __threadfence();   // acquire
    unsigned c8[8]; unsigned cnt = 0;
    const int base1 = 2047 - 8 * tid;
#pragma unroll
    for (int j = 0; j < 8; j++) { c8[j] = __ldcg(&g_hist1[b][base1 - j]); cnt += c8[j]; }
    unsigned pre = bscan(cnt, s_w, tid, lane);
    if (tid == 255) s_total = pre;
    __syncthreads();
    const unsigned total = s_total;
    if (total <= KTOP) {
        if (tid == 0) { g_done[b] = 1; g_kcnt[b] = (float)total; }
    } else {
        if (tid == 0) { g_done[b] = 0; g_kcnt[b] = (float)KTOP; }
        unsigned excl = pre - cnt;
        if (excl < KTOP && pre >= KTOP) {
            unsigned c = excl;
#pragma unroll
            for (int j = 0; j < 8; j++) {
                if (c + c8[j] >= KTOP) { g_b1[b] = base1 - j; g_k2[b] = KTOP - c; break; }
                c += c8[j];
            }
        }
    }
    __syncthreads();
    for (int i = tid; i < 2048; i += 256) g_hist1[b][i] = 0u;   // self-clean
    if (tid == 0) g_arriveA[b] = 0u;
}

// ================= kernel B: refine + hist2 + parallel tail + finalize =======
// grid (BPB, BB), 256 threads, one uint4 per thread
__global__ void __launch_bounds__(256) k_B(float* __restrict__ out) {
    __shared__ unsigned sh3[1024];
    __shared__ unsigned s_w[16];
    __shared__ float s_acc, s_c;
    __shared__ int s_last, s_fin, s_b2;
    __shared__ unsigned s_k3;

    const int b    = blockIdx.y;
    const int tid  = threadIdx.x;
    const int lane = tid & 31;
    const int done = g_done[b];
    const int b1   = g_b1[b];

    const uint4 v = ((const uint4*)g_u)[(size_t)b * NU4 + blockIdx.x * 256 + tid];
    unsigned e[4] = {v.x, v.y, v.z, v.w};
    float s = 0.0f;
#pragma unroll
    for (int q = 0; q < 4; q++) {
        unsigned u = e[q];
        if (!u) continue;
        if (done) {
            s += softplus0(unord(u));
        } else {
            int tb = (int)(u >> 21);
            if (tb > b1) s += softplus0(unord(u));
            else if (tb == b1) {
                unsigned idx = atomicAdd(&g_listn[b], 1u);
                g_list[(size_t)b * NELEM + idx] = u;
                atomicAdd(&g_hist2[b][(u >> 10) & 0x7FFu], 1u);
            }
        }
    }
#pragma unroll
    for (int o = 16; o; o >>= 1) s += __shfl_down_sync(0xffffffffu, s, o);
    if (lane == 0 && s != 0.0f) atomicAdd(&g_topsum[b], s);

    __threadfence();
    __syncthreads();
    if (tid == 0) s_last = (atomicAdd(&g_arriveB[b], 1u) == BPB - 1);
    __syncthreads();
    if (!s_last) return;

    // ---- per-sample parallel tail ----
    __threadfence();   // acquire
    const float kcnt = __ldcg(&g_kcnt[b]);

    if (done) {
        if (tid == 0) g_neg[b] = (kcnt > 0.0f) ? __ldcg(&g_topsum[b]) / kcnt : 0.0f;
        __syncthreads();
    } else {
        const unsigned k2 = __ldcg(&g_k2[b]);
        const unsigned n  = __ldcg(&g_listn[b]);
        const unsigned* lst = g_list + (size_t)b * NELEM;

        // level-2 selection: 8 bins per thread, descending, from g_hist2
        unsigned c8[8]; unsigned cnt = 0;
        const int base2 = 2047 - 8 * tid;
#pragma unroll
        for (int j = 0; j < 8; j++) { c8[j] = __ldcg(&g_hist2[b][base2 - j]); cnt += c8[j]; }
        unsigned pre = bscan(cnt, s_w, tid, lane);
        unsigned excl = pre - cnt;
        if (excl < k2 && pre >= k2) {
            unsigned c = excl;
#pragma unroll
            for (int j = 0; j < 8; j++) {
                if (c + c8[j] >= k2) { s_b2 = base2 - j; s_k3 = k2 - c; break; }
                c += c8[j];
            }
        }
        for (int q = tid; q < 1024; q += 256) sh3[q] = 0u;
        if (tid == 0) { s_acc = 0.0f; s_c = 0.0f; }
        __syncthreads();
        const int b2 = s_b2;
        const unsigned k3 = s_k3;

        // one parallel pass over the compacted list
        float s2 = 0.0f;
        for (unsigned q = tid; q < n; q += 256) {
            unsigned u = __ldcg(&lst[q]);
            int m = (int)((u >> 10) & 0x7FFu);
            if (m > b2) s2 += softplus0(unord(u));
            else if (m == b2) atomicAdd(&sh3[u & 0x3FFu], 1u);
        }
#pragma unroll
        for (int o = 16; o; o >>= 1) s2 += __shfl_down_sync(0xffffffffu, s2, o);
        if (lane == 0 && s2 != 0.0f) atomicAdd(&s_acc, s2);
        __syncthreads();

        // level-3 exact-value bins: 4 bins per thread, parallel softplus
        const unsigned pref = ((unsigned)b1 << 21) | ((unsigned)b2 << 10);
        unsigned c4[4]; unsigned cnt3 = 0; float ws = 0.0f;
        const int base3 = 1023 - 4 * tid;
#pragma unroll
        for (int j = 0; j < 4; j++) {
            unsigned cc = sh3[base3 - j];
            c4[j] = cc; cnt3 += cc;
            if (cc) ws += (float)cc * softplus0(unord(pref | (unsigned)(base3 - j)));
        }
        unsigned pre3 = bscan(cnt3, s_w, tid, lane);
        unsigned excl3 = pre3 - cnt3;
        float contrib = 0.0f;
        if (pre3 <= k3) contrib = ws;
        else if (excl3 < k3) {
            unsigned c = excl3;
#pragma unroll
            for (int j = 0; j < 4; j++) {
                if (!c4[j]) continue;
                float sp = softplus0(unord(pref | (unsigned)(base3 - j)));
                if (c + c4[j] >= k3) { contrib += (float)(k3 - c) * sp; break; }
                contrib += (float)c4[j] * sp;
                c += c4[j];
            }
        }
#pragma unroll
        for (int o = 16; o; o >>= 1) contrib += __shfl_down_sync(0xffffffffu, contrib, o);
        if (lane == 0 && contrib != 0.0f) atomicAdd(&s_c, contrib);
        __syncthreads();
        if (tid == 0) g_neg[b] = (__ldcg(&g_topsum[b]) + s_acc + s_c) / kcnt;
        // self-clean hist2
        for (int q = tid; q < 2048; q += 256) g_hist2[b][q] = 0u;
    }

    // per-sample cleanup, then cross-sample finalize
    if (tid == 0) { g_listn[b] = 0u; g_arriveB[b] = 0u; }
    __threadfence();
    __syncthreads();
    if (tid == 0) s_fin = (atomicAdd(&g_arriveF, 1u) == BB - 1);
    __syncthreads();
    if (s_fin && tid == 0) {
        __threadfence();   // acquire
        float cls = 0.0f, reg = 0.0f, npsum = 0.0f;
        for (int bb = 0; bb < BB; bb++) {
            float np = (float)__ldcg(&g_npos[bb]);
            float pl = (np > 0.0f) ? 5.0f * __ldcg(&g_pos_sum[bb]) / np : 0.0f;
            float rl = (np > 0.0f) ? __ldcg(&g_reg_sum[bb]) / (4.0f * np) : 0.0f;
            cls += pl + __ldcg(&g_neg[bb]);
            reg += rl;
            npsum += np;
            g_pos_sum[bb] = 0.0f; g_reg_sum[bb] = 0.0f;
            g_topsum[bb] = 0.0f;  g_npos[bb] = 0u;
        }
        g_arriveF = 0u;
        cls *= 0.25f;
        reg *= 0.25f;
        out[0] = cls + 0.5f * reg;
        out[1] = cls;
        out[2] = reg;
        out[3] = npsum;
    }
}

// ---------------- launcher ----------------
extern "C" void kernel_launch(void* const* d_in, const int* in_sizes, int n_in,
                              void* d_out, int out_size) {
    const float* pred = (const float*)d_in[0];   // (4,48,48,48,3,5)
    const float* tgt  = (const float*)d_in[1];   // (4,8,4)
    float* out = (float*)d_out;

    dim3 ga(APB, BB);          // 1296 x 4
    k_A<<<ga, 256>>>(pred, tgt);
    dim3 gb(BPB, BB);          // 324 x 4
    k_B<<<gb, 256>>>(out);
}

// round 7
// speedup vs baseline: 1.2107x; 1.0091x over previous
#include <cuda_runtime.h>
#include <cstdint>

#define BB 4
#define GG 8
#define NVOX 110592            /* 48*48*48 */
#define NELEM 331776           /* NVOX*3 */
#define NU4 (NELEM/4)          /* 82944 */
#define KTOP 800
#define APB (NELEM/256)        /* 1296 blocks per sample, kernel A */
#define BPB (NU4/256)          /* 324 blocks per sample, kernel B */

// ---------------- device scratch (static, zero-init, self-cleaning) ----------
__device__ unsigned g_u[BB*NELEM];
__device__ unsigned g_list[BB*NELEM];
__device__ unsigned g_hist1[BB][2048];
__device__ unsigned g_hist2[BB][2048];
__device__ float    g_pos_sum[BB];
__device__ float    g_reg_sum[BB];
__device__ float    g_topsum[BB];
__device__ float    g_neg[BB];
__device__ float    g_kcnt[BB];
__device__ unsigned g_npos[BB];
__device__ unsigned g_k2[BB];
__device__ unsigned g_listn[BB];
__device__ int      g_done[BB];
__device__ int      g_b1[BB];
__device__ unsigned g_arriveA[BB];
__device__ unsigned g_arriveB[BB];
__device__ unsigned g_arriveF;

// ---------------- helpers ----------------
__device__ __forceinline__ float softplus0(float x) {
    return fmaxf(x, 0.0f) + log1pf(expf(-fabsf(x)));
}
__device__ __forceinline__ float sl1(float x) {
    float ax = fabsf(x);
    return (ax < 1.0f) ? 0.5f * x * x : ax - 0.5f;
}
__device__ __forceinline__ unsigned ordmap(float f) {
    unsigned bb = __float_as_uint(f);
    return (bb & 0x80000000u) ? ~bb : (bb | 0x80000000u);
}
__device__ __forceinline__ float unord(unsigned u) {
    unsigned bb = (u & 0x80000000u) ? (u ^ 0x80000000u) : ~u;
    return __uint_as_float(bb);
}
__device__ __forceinline__ unsigned wscan_incl(unsigned v, int lane) {
#pragma unroll
    for (int o = 1; o < 32; o <<= 1) {
        unsigned t = __shfl_up_sync(0xffffffffu, v, o);
        if (lane >= o) v += t;
    }
    return v;
}
// block-wide inclusive scan over 256 threads (thread 0 = topmost chunk).
// s_w must have >= 16 entries; contains garbage afterwards.
__device__ __forceinline__ unsigned bscan(unsigned v, unsigned* s_w, int tid, int lane) {
    unsigned pre = wscan_incl(v, lane);
    if (lane == 31) s_w[tid >> 5] = pre;
    __syncthreads();
    if (tid < 32) {
        unsigned t = (tid < 8) ? s_w[tid] : 0u;
        unsigned p = wscan_incl(t, tid);
        if (tid < 8) s_w[tid + 8] = p - t;      // exclusive warp offset
    }
    __syncthreads();
    return pre + s_w[8 + (tid >> 5)];
}

// ================= kernel A: per-element main pass + parallel level-1 select =
// grid (APB, BB), 256 threads, one (voxel, anchor) element per thread
__global__ void __launch_bounds__(256) k_A(const float* __restrict__ pred,
                                           const float* __restrict__ tgt) {
    __shared__ float s_gxp[GG], s_gxm[GG], s_gyp[GG], s_gym[GG], s_gzp[GG], s_gzm[GG];
    __shared__ float s_gx[GG], s_gy[GG], s_gz[GG], s_gd[GG], s_d3[GG];
    __shared__ unsigned s_hist[2048];
    __shared__ unsigned s_w[16];
    __shared__ unsigned s_total;
    __shared__ int s_last;

    const int b    = blockIdx.y;
    const int tid  = threadIdx.x;
    const int lane = tid & 31;

    if (tid < GG) {
        const float* t = tgt + (b * GG + tid) * 4;
        float gx = t[0], gy = t[1], gz = t[2], gd = t[3];
        float r2 = 0.5f * gd;
        s_gx[tid] = gx; s_gy[tid] = gy; s_gz[tid] = gz; s_gd[tid] = gd;
        s_gxp[tid] = gx + r2; s_gxm[tid] = gx - r2;
        s_gyp[tid] = gy + r2; s_gym[tid] = gy - r2;
        s_gzp[tid] = gz + r2; s_gzm[tid] = gz - r2;
        s_d3[tid] = gd * gd * gd;
    }
    for (int i = tid; i < 2048; i += 256) s_hist[i] = 0u;
    __syncthreads();

    const int e   = blockIdx.x * 256 + tid;          // element = vox*3 + a
    const int vox = e / 3;
    const int a   = e - vox * 3;
    const int w = vox % 48; const int t2 = vox / 48;
    const int h = t2 % 48;  const int d = t2 / 48;
    const float cx = (float)(w * 4 + 2);
    const float cy = (float)(h * 4 + 2);
    const float cz = (float)(d * 4 + 2);

    const float r1 = 2.5f * (float)(1 << a);                         // anchor/2
    const float a3 = 125.0f * (float)(1 << (3 * a));                 // anchor^3
    const float ia = __uint_as_float(0x3E4CCCCDu - ((unsigned)a << 23)); // 0.2/2^a

    const float* p = pred + ((size_t)b * NELEM + (size_t)e) * 5;
    const float conf = p[0];

    float bi = -1.0f, bu = 1.0f;
    int bidx = 0;
#pragma unroll
    for (int g = 0; g < GG; g++) {
        float ix = fminf(cx + r1, s_gxp[g]) - fmaxf(cx - r1, s_gxm[g]); ix = fmaxf(ix, 0.0f);
        float iy = fminf(cy + r1, s_gyp[g]) - fmaxf(cy - r1, s_gym[g]); iy = fmaxf(iy, 0.0f);
        float iz = fminf(cz + r1, s_gzp[g]) - fmaxf(cz - r1, s_gzm[g]); iz = fmaxf(iz, 0.0f);
        float inter = ix * iy * iz;
        float un = a3 + s_d3[g] - inter + 1e-6f;
        if (inter * bu > bi * un) { bi = inter; bu = un; bidx = g; }
    }

    const bool pos = bi > 0.5f  * bu;
    const bool neg = bi < 0.02f * bu;
    unsigned u = 0u;
    if (neg) { u = ordmap(conf); atomicAdd(&s_hist[u >> 21], 1u); }
    g_u[(size_t)b * NELEM + e] = u;

    float lpos = 0.0f, lreg = 0.0f;
    unsigned lnp = 0;
    if (pos) {
        lnp = 1;
        lpos = fmaxf(conf, 0.0f) - conf + log1pf(expf(-fabsf(conf)));
        int g = bidx;
        float tx = (s_gx[g] - cx) * ia;
        float ty = (s_gy[g] - cy) * ia;
        float tz = (s_gz[g] - cz) * ia;
        float td = logf(s_gd[g] * ia);
        lreg = sl1(p[1] - tx) + sl1(p[2] - ty) + sl1(p[3] - tz) + sl1(p[4] - td);
    }
#pragma unroll
    for (int o = 16; o; o >>= 1) {
        lpos += __shfl_down_sync(0xffffffffu, lpos, o);
        lreg += __shfl_down_sync(0xffffffffu, lreg, o);
        lnp  += __shfl_down_sync(0xffffffffu, lnp, o);
    }
    if (lane == 0 && lnp) {
        atomicAdd(&g_pos_sum[b], lpos);
        atomicAdd(&g_reg_sum[b], lreg);
        atomicAdd(&g_npos[b], lnp);
    }
    __syncthreads();
    for (int i = tid; i < 2048; i += 256) {
        unsigned c = s_hist[i];
        if (c) atomicAdd(&g_hist1[b][i], c);
    }
    __threadfence();
    __syncthreads();
    if (tid == 0) s_last = (atomicAdd(&g_arriveA[b], 1u) == APB - 1);
    __syncthreads();
    if (!s_last) return;

    // ---- parallel level-1 selection: 8 bins per thread, descending ----
    __threadfence();   // acquire
    unsigned c8[8]; unsigned cnt = 0;
    const int base1 = 2047 - 8 * tid;
#pragma unroll
    for (int j = 0; j < 8; j++) { c8[j] = __ldcg(&g_hist1[b][base1 - j]); cnt += c8[j]; }
    unsigned pre = bscan(cnt, s_w, tid, lane);
    if (tid == 255) s_total = pre;
    __syncthreads();
    const unsigned total = s_total;
    if (total <= KTOP) {
        if (tid == 0) { g_done[b] = 1; g_kcnt[b] = (float)total; }
    } else {
        if (tid == 0) { g_done[b] = 0; g_kcnt[b] = (float)KTOP; }
        unsigned excl = pre - cnt;
        if (excl < KTOP && pre >= KTOP) {
            unsigned c = excl;
#pragma unroll
            for (int j = 0; j < 8; j++) {
                if (c + c8[j] >= KTOP) { g_b1[b] = base1 - j; g_k2[b] = KTOP - c; break; }
                c += c8[j];
            }
        }
    }
    __syncthreads();
    for (int i = tid; i < 2048; i += 256) g_hist1[b][i] = 0u;   // self-clean
    if (tid == 0) g_arriveA[b] = 0u;
}

// ================= kernel B: refine + hist2 + parallel tail + finalize =======
// grid (BPB, BB), 256 threads, one uint4 per thread
__global__ void __launch_bounds__(256) k_B(float* __restrict__ out) {
    __shared__ unsigned sh3[1024];
    __shared__ unsigned s_w[16];
    __shared__ float s_acc, s_c;
    __shared__ int s_last, s_fin, s_b2;
    __shared__ unsigned s_k3;

    const int b    = blockIdx.y;
    const int tid  = threadIdx.x;
    const int lane = tid & 31;
    const int done = g_done[b];
    const int b1   = g_b1[b];

    const uint4 v = ((const uint4*)g_u)[(size_t)b * NU4 + blockIdx.x * 256 + tid];
    unsigned e[4] = {v.x, v.y, v.z, v.w};
    float s = 0.0f;
#pragma unroll
    for (int q = 0; q < 4; q++) {
        unsigned u = e[q];
        if (!u) continue;
        if (done) {
            s += softplus0(unord(u));
        } else {
            int tb = (int)(u >> 21);
            if (tb > b1) s += softplus0(unord(u));
            else if (tb == b1) {
                unsigned idx = atomicAdd(&g_listn[b], 1u);
                g_list[(size_t)b * NELEM + idx] = u;
                atomicAdd(&g_hist2[b][(u >> 10) & 0x7FFu], 1u);
            }
        }
    }
#pragma unroll
    for (int o = 16; o; o >>= 1) s += __shfl_down_sync(0xffffffffu, s, o);
    if (lane == 0 && s != 0.0f) atomicAdd(&g_topsum[b], s);

    __threadfence();
    __syncthreads();
    if (tid == 0) s_last = (atomicAdd(&g_arriveB[b], 1u) == BPB - 1);
    __syncthreads();
    if (!s_last) return;

    // ---- per-sample parallel tail ----
    __threadfence();   // acquire
    const float kcnt = __ldcg(&g_kcnt[b]);

    if (done) {
        if (tid == 0) g_neg[b] = (kcnt > 0.0f) ? __ldcg(&g_topsum[b]) / kcnt : 0.0f;
        __syncthreads();
    } else {
        const unsigned k2 = __ldcg(&g_k2[b]);
        const unsigned n  = __ldcg(&g_listn[b]);
        const unsigned* lst = g_list + (size_t)b * NELEM;

        // level-2 selection: 8 bins per thread, descending, from g_hist2
        unsigned c8[8]; unsigned cnt = 0;
        const int base2 = 2047 - 8 * tid;
#pragma unroll
        for (int j = 0; j < 8; j++) { c8[j] = __ldcg(&g_hist2[b][base2 - j]); cnt += c8[j]; }
        unsigned pre = bscan(cnt, s_w, tid, lane);
        unsigned excl = pre - cnt;
        if (excl < k2 && pre >= k2) {
            unsigned c = excl;
#pragma unroll
            for (int j = 0; j < 8; j++) {
                if (c + c8[j] >= k2) { s_b2 = base2 - j; s_k3 = k2 - c; break; }
                c += c8[j];
            }
        }
        for (int q = tid; q < 1024; q += 256) sh3[q] = 0u;
        if (tid == 0) { s_acc = 0.0f; s_c = 0.0f; }
        __syncthreads();
        const int b2 = s_b2;
        const unsigned k3 = s_k3;

        // one parallel pass over the compacted list
        float s2 = 0.0f;
        for (unsigned q = tid; q < n; q += 256) {
            unsigned u = __ldcg(&lst[q]);
            int m = (int)((u >> 10) & 0x7FFu);
            if (m > b2) s2 += softplus0(unord(u));
            else if (m == b2) atomicAdd(&sh3[u & 0x3FFu], 1u);
        }
#pragma unroll
        for (int o = 16; o; o >>= 1) s2 += __shfl_down_sync(0xffffffffu, s2, o);
        if (lane == 0 && s2 != 0.0f) atomicAdd(&s_acc, s2);
        __syncthreads();

        // level-3 exact-value bins: 4 bins per thread, parallel softplus
        const unsigned pref = ((unsigned)b1 << 21) | ((unsigned)b2 << 10);
        unsigned c4[4]; unsigned cnt3 = 0; float ws = 0.0f;
        const int base3 = 1023 - 4 * tid;
#pragma unroll
        for (int j = 0; j < 4; j++) {
            unsigned cc = sh3[base3 - j];
            c4[j] = cc; cnt3 += cc;
            if (cc) ws += (float)cc * softplus0(unord(pref | (unsigned)(base3 - j)));
        }
        unsigned pre3 = bscan(cnt3, s_w, tid, lane);
        unsigned excl3 = pre3 - cnt3;
        float contrib = 0.0f;
        if (pre3 <= k3) contrib = ws;
        else if (excl3 < k3) {
            unsigned c = excl3;
#pragma unroll
            for (int j = 0; j < 4; j++) {
                if (!c4[j]) continue;
                float sp = softplus0(unord(pref | (unsigned)(base3 - j)));
                if (c + c4[j] >= k3) { contrib += (float)(k3 - c) * sp; break; }
                contrib += (float)c4[j] * sp;
                c += c4[j];
            }
        }
#pragma unroll
        for (int o = 16; o; o >>= 1) contrib += __shfl_down_sync(0xffffffffu, contrib, o);
        if (lane == 0 && contrib != 0.0f) atomicAdd(&s_c, contrib);
        __syncthreads();
        if (tid == 0) g_neg[b] = (__ldcg(&g_topsum[b]) + s_acc + s_c) / kcnt;
        // self-clean hist2
        for (int q = tid; q < 2048; q += 256) g_hist2[b][q] = 0u;
    }

    // per-sample cleanup, then cross-sample finalize
    if (tid == 0) { g_listn[b] = 0u; g_arriveB[b] = 0u; }
    __threadfence();
    __syncthreads();
    if (tid == 0) s_fin = (atomicAdd(&g_arriveF, 1u) == BB - 1);
    __syncthreads();
    if (s_fin && tid == 0) {
        __threadfence();   // acquire
        float cls = 0.0f, reg = 0.0f, npsum = 0.0f;
        for (int bb = 0; bb < BB; bb++) {
            float np = (float)__ldcg(&g_npos[bb]);
            float pl = (np > 0.0f) ? 5.0f * __ldcg(&g_pos_sum[bb]) / np : 0.0f;
            float rl = (np > 0.0f) ? __ldcg(&g_reg_sum[bb]) / (4.0f * np) : 0.0f;
            cls += pl + __ldcg(&g_neg[bb]);
            reg += rl;
            npsum += np;
            g_pos_sum[bb] = 0.0f; g_reg_sum[bb] = 0.0f;
            g_topsum[bb] = 0.0f;  g_npos[bb] = 0u;
        }
        g_arriveF = 0u;
        cls *= 0.25f;
        reg *= 0.25f;
        out[0] = cls + 0.5f * reg;
        out[1] = cls;
        out[2] = reg;
        out[3] = npsum;
    }
}

// ---------------- launcher ----------------
extern "C" void kernel_launch(void* const* d_in, const int* in_sizes, int n_in,
                              void* d_out, int out_size) {
    const float* pred = (const float*)d_in[0];   // (4,48,48,48,3,5)
    const float* tgt  = (const float*)d_in[1];   // (4,8,4)
    float* out = (float*)d_out;

    dim3 ga(APB, BB);          // 1296 x 4
    k_A<<<ga, 256>>>(pred, tgt);
    dim3 gb(BPB, BB);          // 324 x 4
    k_B<<<gb, 256>>>(out);
}